// round 10
// baseline (speedup 1.0000x reference)
#include <cuda_runtime.h>

#define BATCH  8
#define SEQ    4096
#define DMODEL 512

// Grid = 2048 CTAs x 128 threads. CTA i handles positions s0=i and s1=i+2048;
// each thread owns 4 contiguous d's (float4). All 16 table gathers (2 pos x 8
// batch) are issued front-batched (per-thread MLP=16) before any result is
// consumed; PE for BOTH positions is computed in the shadow of those loads,
// sharing the d-dependent exp2f term. Evidence (R2 vs R8): dur tracks
// in-flight loads, not occupancy -> maximize MLP, accept 37% occ.
__global__ void __launch_bounds__(128, 6)
embed_pe_kernel(const int* __restrict__ tokens,
                const float* __restrict__ table,
                float* __restrict__ out)
{
    const int s0 = blockIdx.x;          // 0..2047
    const int s1 = s0 + 2048;
    const int t  = threadIdx.x;         // 0..127
    const int d0 = t << 2;              // 0,4,...,508

    // token ids (uniform per CTA -> broadcast LDG)
    int tokA[BATCH], tokB[BATCH];
#pragma unroll
    for (int b = 0; b < BATCH; ++b) tokA[b] = __ldg(tokens + b * SEQ + s0);
#pragma unroll
    for (int b = 0; b < BATCH; ++b) tokB[b] = __ldg(tokens + b * SEQ + s1);

    // fire all 16 gathers back-to-back (MLP=16)
    float4 eA[BATCH], eB[BATCH];
#pragma unroll
    for (int b = 0; b < BATCH; ++b)
        eA[b] = *reinterpret_cast<const float4*>(
            table + (size_t)tokA[b] * DMODEL + d0);
#pragma unroll
    for (int b = 0; b < BATCH; ++b)
        eB[b] = *reinterpret_cast<const float4*>(
            table + (size_t)tokB[b] * DMODEL + d0);

    // PE for both positions in the shadow of the loads.
    // inv_w = 10000^(-2*i/512) depends only on d -> shared.
    float peA[4], peB[4];
#pragma unroll
    for (int j = 0; j < 4; ++j) {
        const float fi    = (float)(d0 + j);
        const float inv_w = exp2f(fi * (-2.0f / (float)DMODEL) * 13.287712379549449f);
        const float aA = (float)s0 * inv_w;
        const float aB = (float)s1 * inv_w;
        if ((d0 + j) & 1) { peA[j] = cosf(aA); peB[j] = cosf(aB); }
        else              { peA[j] = sinf(aA); peB[j] = sinf(aB); }
    }

    // add + streaming stores (keep the table L2-resident)
#pragma unroll
    for (int b = 0; b < BATCH; ++b) {
        float4 o;
        o.x = eA[b].x + peA[0];
        o.y = eA[b].y + peA[1];
        o.z = eA[b].z + peA[2];
        o.w = eA[b].w + peA[3];
        __stcs(reinterpret_cast<float4*>(
                   out + ((size_t)(b * SEQ + s0)) * DMODEL + d0), o);
    }
#pragma unroll
    for (int b = 0; b < BATCH; ++b) {
        float4 o;
        o.x = eB[b].x + peB[0];
        o.y = eB[b].y + peB[1];
        o.z = eB[b].z + peB[2];
        o.w = eB[b].w + peB[3];
        __stcs(reinterpret_cast<float4*>(
                   out + ((size_t)(b * SEQ + s1)) * DMODEL + d0), o);
    }
}

extern "C" void kernel_launch(void* const* d_in, const int* in_sizes, int n_in,
                              void* d_out, int out_size)
{
    const int*   tokens = (const int*)d_in[0];   // [B, S] int32
    const float* table  = (const float*)d_in[1]; // [VOCAB, D] f32
    float*       out    = (float*)d_out;         // [B, S, D] f32
    (void)in_sizes; (void)n_in; (void)out_size;

    embed_pe_kernel<<<SEQ / 2, 128>>>(tokens, table, out);
}